// round 12
// baseline (speedup 1.0000x reference)
#include <cuda_runtime.h>
#include <cuda_fp16.h>
#include <cstdint>

#define CIN   32
#define COUT  64
#define TT    8
#define DDIM  32
#define HDIM  64
#define WDIM  64

// xs2: [cp(8)][row(30 = 3d x 10h)][wc(68)] half2 words (channels 2cp,2cp+1 packed)
#define CPSTRIDE (30 * 68)             // 2040 words per cp plane
#define XS2_SIZE (8 * CPSTRIDE)        // 16320 words
#define SMEM_BYTES (XS2_SIZE * 4)      // 65280 B -> 2 blocks/SM

// fused weights, fp16 frag layout: g_w2[((b*2+cg)*27+s)*32+lane][16 u32]
// word r = nf*2+half : half2{ w'[o][cA], w'[o][cA+1] },
//   o = nf*8 + (lane>>2), cA = cg*16 + half*8 + 2*(lane&3)
__device__ uint32_t g_w2[4 * 2 * 27 * 32 * 16];   // 110592 u32

__device__ __forceinline__ uint32_t smem_u32(const void* p) {
    uint32_t a;
    asm("{ .reg .u64 t; cvta.to.shared.u64 t, %1; cvt.u32.u64 %0, t; }" : "=r"(a) : "l"(p));
    return a;
}
__device__ __forceinline__ uint32_t lds32(uint32_t a) {
    uint32_t v; asm volatile("ld.shared.b32 %0, [%1];" : "=r"(v) : "r"(a)); return v;
}
__device__ __forceinline__ void mma_f16(float* c,
                                        uint32_t a0, uint32_t a1, uint32_t a2, uint32_t a3,
                                        uint32_t b0, uint32_t b1) {
    asm volatile("mma.sync.aligned.m16n8k16.row.col.f32.f16.f16.f32 "
                 "{%0,%1,%2,%3}, {%4,%5,%6,%7}, {%8,%9}, {%0,%1,%2,%3};"
                 : "+f"(c[0]), "+f"(c[1]), "+f"(c[2]), "+f"(c[3])
                 : "r"(a0), "r"(a1), "r"(a2), "r"(a3), "r"(b0), "r"(b1));
}

// ---------- init: w'[b,o,c,s] = sum_t weight[o,c,t]*stencils[b,t,s] -> fp16 frags ----------
__global__ void init_w2_kernel(const float* __restrict__ weight,
                               const float* __restrict__ stencils) {
    int idx  = blockIdx.x * 256 + threadIdx.x;   // 0 .. 110591
    int r    = idx & 15;
    int lane = (idx >> 4) & 31;
    int s    = (idx >> 9) % 27;
    int rest = (idx >> 9) / 27;                  // b*2 + cg
    int cg = rest & 1, b = rest >> 1;
    int nf = r >> 1, half = r & 1;
    int o  = nf * 8 + (lane >> 2);
    int cA = cg * 16 + half * 8 + 2 * (lane & 3);
    float va = 0.f, vb = 0.f;
    #pragma unroll
    for (int t = 0; t < TT; t++) {
        float st = stencils[(b * TT + t) * 27 + s];
        va += weight[(o * CIN + cA) * TT + t] * st;
        vb += weight[(o * CIN + cA + 1) * TT + t] * st;
    }
    __half2 h = __floats2half2_rn(va, vb);
    g_w2[idx] = *reinterpret_cast<uint32_t*>(&h);
}

__global__ __launch_bounds__(512, 2)
void stencilconv3d_kernel(const float* __restrict__ x,
                          const float* __restrict__ bias,
                          float* __restrict__ out) {
    extern __shared__ uint32_t sm[];
    const uint32_t smb = smem_u32(sm);

    const int h0  = blockIdx.x;   // 0..7 (8 output h rows per block)
    const int d0  = blockIdx.y;   // 0..31
    const int bz  = blockIdx.z;   // 0..3
    const int tid = threadIdx.x;
    const int wid = tid >> 5;     // 0..15
    const int lane = tid & 31;

    // warp mapping: hl = h row (0..7), oh = o half (0..1)
    const int hl = wid >> 1;
    const int oh = wid & 1;

    // thread-invariant part of A-frag address (bytes); warp's h row = hl
    const uint32_t poff = smb + (uint32_t)((lane & 3) * CPSTRIDE + hl * 68
                                           + (lane >> 2)) * 4u;

    float acc[4][4][4];           // [m-frag(16 w each)][n-frag(8 o, this half)][c]
    #pragma unroll
    for (int i = 0; i < 4; i++)
        #pragma unroll
        for (int j = 0; j < 4; j++)
            #pragma unroll
            for (int c = 0; c < 4; c++) acc[i][j][c] = 0.f;

    const size_t x_plane = (size_t)DDIM * HDIM * WDIM;
    const int hbase = h0 * 8 - 1;

    #pragma unroll 1
    for (int cg = 0; cg < 2; cg++) {
        __syncthreads();   // xs2 free for reuse

        // ---- load x: 16 channels as 8 half2 planes, 30 rows x 68 w, zero-padded ----
        const float* xc = x + ((size_t)bz * CIN + (size_t)cg * 16) * x_plane;
        {
            int wc = tid % 68;
            int hq = tid / 68;           // 0..7
            int dz = 0, cp = 0;
            for (int idx = tid; idx < XS2_SIZE; idx += 512) {
                int dg = d0 + dz - 1;
                int hg = hbase + hq;
                int wg = wc - 1;
                float v0 = 0.f, v1 = 0.f;
                if (wc < 66 && (unsigned)dg < DDIM && (unsigned)hg < HDIM && (unsigned)wg < WDIM) {
                    const float* p0 = xc + (size_t)(2 * cp) * x_plane
                                    + ((size_t)dg * HDIM + hg) * WDIM + wg;
                    v0 = p0[0];
                    v1 = p0[x_plane];
                }
                __half2 h = __floats2half2_rn(v0, v1);
                sm[idx] = *reinterpret_cast<uint32_t*>(&h);
                // advance by 512 = 7*68 + 36
                wc += 36; hq += 7;
                if (wc >= 68) { wc -= 68; hq++; }
                if (hq >= 10) { hq -= 10; dz++; }
                if (dz >= 3)  { dz -= 3; cp++; }
            }
        }
        __syncthreads();

        // ---- GEMM: 27 k16-steps (one per stencil offset s), fully unrolled ----
        const uint4* wp = (const uint4*)g_w2
                        + ((size_t)((bz * 2 + cg) * 27) * 32 + lane) * 4 + oh * 2;
        #pragma unroll
        for (int s = 0; s < 27; s++) {
            const int rowoff = (((s / 9) * 10 + ((s % 9) / 3)) * 68 + (s % 3)) * 4;
            uint32_t af[4][4];
            #pragma unroll
            for (int mf = 0; mf < 4; mf++) {
                uint32_t ab = poff + (uint32_t)rowoff + (uint32_t)mf * 64u;
                af[mf][0] = lds32(ab);
                af[mf][1] = lds32(ab + 32u);                 // +8 w points
                af[mf][2] = lds32(ab + 4u * CPSTRIDE * 4u);  // +4 cp planes (k+8)
                af[mf][3] = lds32(ab + 4u * CPSTRIDE * 4u + 32u);
            }
            const uint4* wps = wp + (size_t)s * 128;         // 32 lanes * 4 uint4
            uint4 q0 = __ldg(wps + 0);      // nf_local 0,1
            uint4 q1 = __ldg(wps + 1);      // nf_local 2,3
            #pragma unroll
            for (int mf = 0; mf < 4; mf++) {
                mma_f16(acc[mf][0], af[mf][0], af[mf][1], af[mf][2], af[mf][3], q0.x, q0.y);
                mma_f16(acc[mf][1], af[mf][0], af[mf][1], af[mf][2], af[mf][3], q0.z, q0.w);
                mma_f16(acc[mf][2], af[mf][0], af[mf][1], af[mf][2], af[mf][3], q1.x, q1.y);
                mma_f16(acc[mf][3], af[mf][0], af[mf][1], af[mf][2], af[mf][3], q1.z, q1.w);
            }
        }
    }

    // ---- epilogue: registers -> gmem, + bias ----
    {
        const size_t ostride = (size_t)DDIM * HDIM * WDIM;
        const int h = h0 * 8 + hl;
        const size_t obase = (size_t)bz * COUT * ostride
                           + (size_t)d0 * HDIM * WDIM + (size_t)h * WDIM;
        #pragma unroll
        for (int nf = 0; nf < 4; nf++) {
            int o0 = oh * 32 + nf * 8 + (lane & 3) * 2;
            float bv0 = __ldg(&bias[o0]);
            float bv1 = __ldg(&bias[o0 + 1]);
            #pragma unroll
            for (int mf = 0; mf < 4; mf++) {
                #pragma unroll
                for (int cc = 0; cc < 4; cc++) {
                    float sv = acc[mf][nf][cc];
                    int o = o0 + (cc & 1);
                    int w = mf * 16 + (lane >> 2) + ((cc >> 1) & 1) * 8;
                    out[obase + (size_t)o * ostride + w]
                        = sv + ((cc & 1) ? bv1 : bv0);
                }
            }
        }
    }
}

extern "C" void kernel_launch(void* const* d_in, const int* in_sizes, int n_in,
                              void* d_out, int out_size) {
    const float* x        = (const float*)d_in[0];
    const float* stencils = (const float*)d_in[1];
    const float* weight   = (const float*)d_in[2];
    const float* bias     = (const float*)d_in[3];
    float* out = (float*)d_out;

    init_w2_kernel<<<432, 256>>>(weight, stencils);

    cudaFuncSetAttribute(stencilconv3d_kernel,
                         cudaFuncAttributeMaxDynamicSharedMemorySize, SMEM_BYTES);
    dim3 grid(HDIM / 8, DDIM, 4);   // 8 x 32 x 4 = 1024 blocks
    stencilconv3d_kernel<<<grid, 512, SMEM_BYTES>>>(x, bias, out);
}

// round 13
// speedup vs baseline: 3.1753x; 3.1753x over previous
#include <cuda_runtime.h>
#include <cuda_fp16.h>
#include <cstdint>

#define CIN   32
#define COUT  64
#define TT    8
#define DDIM  32
#define HDIM  64
#define WDIM  64

// xs2: [cp(8)][row(18 = 3d x 6h)][wc(68)] half2 words (channels 2cp,2cp+1 packed)
#define CPSTRIDE (18 * 68)             // 1224 words per cp plane
#define XS2_SIZE (8 * CPSTRIDE)        // 9792 words
#define SMEM_BYTES (XS2_SIZE * 4)      // 39168 B -> 2 blocks/SM

// fused weights, fp16 frag layout: g_w2[((b*2+cg)*27+s)*32+lane][16 u32]
// word r = nf*2+half : half2{ w'[o][cA], w'[o][cA+1] },
//   o = nf*8 + (lane>>2), cA = cg*16 + half*8 + 2*(lane&3)
__device__ uint32_t g_w2[4 * 2 * 27 * 32 * 16];   // 110592 u32

__device__ __forceinline__ uint32_t smem_u32(const void* p) {
    uint32_t a;
    asm("{ .reg .u64 t; cvta.to.shared.u64 t, %1; cvt.u32.u64 %0, t; }" : "=r"(a) : "l"(p));
    return a;
}
__device__ __forceinline__ uint32_t lds32(uint32_t a) {
    uint32_t v; asm volatile("ld.shared.b32 %0, [%1];" : "=r"(v) : "r"(a)); return v;
}
__device__ __forceinline__ void mma_f16(float* c,
                                        uint32_t a0, uint32_t a1, uint32_t a2, uint32_t a3,
                                        uint32_t b0, uint32_t b1) {
    asm volatile("mma.sync.aligned.m16n8k16.row.col.f32.f16.f16.f32 "
                 "{%0,%1,%2,%3}, {%4,%5,%6,%7}, {%8,%9}, {%0,%1,%2,%3};"
                 : "+f"(c[0]), "+f"(c[1]), "+f"(c[2]), "+f"(c[3])
                 : "r"(a0), "r"(a1), "r"(a2), "r"(a3), "r"(b0), "r"(b1));
}

// ---------- init: w'[b,o,c,s] = sum_t weight[o,c,t]*stencils[b,t,s] -> fp16 frags ----------
__global__ void init_w2_kernel(const float* __restrict__ weight,
                               const float* __restrict__ stencils) {
    int idx  = blockIdx.x * 256 + threadIdx.x;   // 0 .. 110591
    int r    = idx & 15;
    int lane = (idx >> 4) & 31;
    int s    = (idx >> 9) % 27;
    int rest = (idx >> 9) / 27;                  // b*2 + cg
    int cg = rest & 1, b = rest >> 1;
    int nf = r >> 1, half = r & 1;
    int o  = nf * 8 + (lane >> 2);
    int cA = cg * 16 + half * 8 + 2 * (lane & 3);
    float va = 0.f, vb = 0.f;
    #pragma unroll
    for (int t = 0; t < TT; t++) {
        float st = stencils[(b * TT + t) * 27 + s];
        va += weight[(o * CIN + cA) * TT + t] * st;
        vb += weight[(o * CIN + cA + 1) * TT + t] * st;
    }
    __half2 h = __floats2half2_rn(va, vb);
    g_w2[idx] = *reinterpret_cast<uint32_t*>(&h);
}

__global__ __launch_bounds__(256, 2)
void stencilconv3d_kernel(const float* __restrict__ x,
                          const float* __restrict__ bias,
                          float* __restrict__ out) {
    extern __shared__ uint32_t sm[];
    const uint32_t smb = smem_u32(sm);

    const int h0  = blockIdx.x;   // 0..15 (4 output h rows)
    const int d0  = blockIdx.y;   // 0..31
    const int bz  = blockIdx.z;   // 0..3
    const int tid = threadIdx.x;
    const int wid = tid >> 5;     // 0..7
    const int lane = tid & 31;

    // warp mapping: hl = h row (0..3), oh = o half (0..1)
    const int hl = wid >> 1;
    const int oh = wid & 1;

    // thread-invariant part of A-frag address (bytes); warp's h row = hl
    const uint32_t poff = smb + (uint32_t)((lane & 3) * CPSTRIDE + hl * 68
                                           + (lane >> 2)) * 4u;

    float acc[4][4][4];           // [m-frag(16 w each)][n-frag(8 o, this half)][c]
    #pragma unroll
    for (int i = 0; i < 4; i++)
        #pragma unroll
        for (int j = 0; j < 4; j++)
            #pragma unroll
            for (int c = 0; c < 4; c++) acc[i][j][c] = 0.f;

    const size_t x_plane = (size_t)DDIM * HDIM * WDIM;
    const int hbase = h0 * 4 - 1;

    #pragma unroll 1
    for (int cg = 0; cg < 2; cg++) {
        __syncthreads();   // xs2 free for reuse

        // ---- load x: 16 channels as 8 half2 planes, 18 rows x 68 w, zero-padded ----
        const float* xc = x + ((size_t)bz * CIN + (size_t)cg * 16) * x_plane;
        {
            int wc = tid % 68;
            int hq = tid / 68;           // 0..3
            int dz = 0, cp = 0;
            for (int idx = tid; idx < XS2_SIZE; idx += 256) {
                int dg = d0 + dz - 1;
                int hg = hbase + hq;
                int wg = wc - 1;
                float v0 = 0.f, v1 = 0.f;
                if (wc < 66 && (unsigned)dg < DDIM && (unsigned)hg < HDIM && (unsigned)wg < WDIM) {
                    const float* p0 = xc + (size_t)(2 * cp) * x_plane
                                    + ((size_t)dg * HDIM + hg) * WDIM + wg;
                    v0 = p0[0];
                    v1 = p0[x_plane];
                }
                __half2 h = __floats2half2_rn(v0, v1);
                sm[idx] = *reinterpret_cast<uint32_t*>(&h);
                // advance by 256 = 3*68 + 52
                wc += 52; hq += 3;
                if (wc >= 68) { wc -= 68; hq++; }
                if (hq >= 6)  { hq -= 6; dz++; }
                if (dz >= 3)  { dz -= 3; cp++; }
            }
        }
        __syncthreads();

        // ---- GEMM: 27 k16-steps, B software-pipelined 2 deep ----
        const uint4* wp = (const uint4*)g_w2
                        + ((size_t)((bz * 2 + cg) * 27) * 32 + lane) * 4 + oh * 2;
        uint4 qbuf[2][2];
        qbuf[0][0] = __ldg(wp + 0);         qbuf[0][1] = __ldg(wp + 1);
        qbuf[1][0] = __ldg(wp + 128);       qbuf[1][1] = __ldg(wp + 129);
        #pragma unroll
        for (int s = 0; s < 27; s++) {
            const int rowoff = (((s / 9) * 6 + ((s % 9) / 3)) * 68 + (s % 3)) * 4;
            uint32_t af[4][4];
            #pragma unroll
            for (int mf = 0; mf < 4; mf++) {
                uint32_t ab = poff + (uint32_t)rowoff + (uint32_t)mf * 64u;
                af[mf][0] = lds32(ab);
                af[mf][1] = lds32(ab + 32u);                 // +8 w points
                af[mf][2] = lds32(ab + 4u * CPSTRIDE * 4u);  // +4 cp planes (k+8)
                af[mf][3] = lds32(ab + 4u * CPSTRIDE * 4u + 32u);
            }
            uint4 q0 = qbuf[s & 1][0];
            uint4 q1 = qbuf[s & 1][1];
            if (s + 2 < 27) {                                // prefetch step s+2
                qbuf[s & 1][0] = __ldg(wp + (size_t)(s + 2) * 128);
                qbuf[s & 1][1] = __ldg(wp + (size_t)(s + 2) * 128 + 1);
            }
            #pragma unroll
            for (int mf = 0; mf < 4; mf++) {
                mma_f16(acc[mf][0], af[mf][0], af[mf][1], af[mf][2], af[mf][3], q0.x, q0.y);
                mma_f16(acc[mf][1], af[mf][0], af[mf][1], af[mf][2], af[mf][3], q0.z, q0.w);
                mma_f16(acc[mf][2], af[mf][0], af[mf][1], af[mf][2], af[mf][3], q1.x, q1.y);
                mma_f16(acc[mf][3], af[mf][0], af[mf][1], af[mf][2], af[mf][3], q1.z, q1.w);
            }
        }
    }

    // ---- epilogue: registers -> gmem, + bias ----
    {
        const size_t ostride = (size_t)DDIM * HDIM * WDIM;
        const int h = h0 * 4 + hl;
        const size_t obase = (size_t)bz * COUT * ostride
                           + (size_t)d0 * HDIM * WDIM + (size_t)h * WDIM;
        #pragma unroll
        for (int nf = 0; nf < 4; nf++) {
            int o0 = oh * 32 + nf * 8 + (lane & 3) * 2;
            float bv0 = __ldg(&bias[o0]);
            float bv1 = __ldg(&bias[o0 + 1]);
            #pragma unroll
            for (int mf = 0; mf < 4; mf++) {
                #pragma unroll
                for (int cc = 0; cc < 4; cc++) {
                    float sv = acc[mf][nf][cc];
                    int o = o0 + (cc & 1);
                    int w = mf * 16 + (lane >> 2) + ((cc >> 1) & 1) * 8;
                    out[obase + (size_t)o * ostride + w]
                        = sv + ((cc & 1) ? bv1 : bv0);
                }
            }
        }
    }
}

extern "C" void kernel_launch(void* const* d_in, const int* in_sizes, int n_in,
                              void* d_out, int out_size) {
    const float* x        = (const float*)d_in[0];
    const float* stencils = (const float*)d_in[1];
    const float* weight   = (const float*)d_in[2];
    const float* bias     = (const float*)d_in[3];
    float* out = (float*)d_out;

    init_w2_kernel<<<432, 256>>>(weight, stencils);

    cudaFuncSetAttribute(stencilconv3d_kernel,
                         cudaFuncAttributeMaxDynamicSharedMemorySize, SMEM_BYTES);
    dim3 grid(HDIM / 4, DDIM, 4);   // 16 x 32 x 4 = 2048 blocks
    stencilconv3d_kernel<<<grid, 256, SMEM_BYTES>>>(x, bias, out);
}

// round 14
// speedup vs baseline: 3.2076x; 1.0101x over previous
#include <cuda_runtime.h>
#include <cuda_fp16.h>
#include <cstdint>

#define CIN   32
#define COUT  64
#define TT    8
#define DDIM  32
#define HDIM  64
#define WDIM  64

// xs2: [cp(16)][row(18 = 3d x 6h)][wc(68)] half2 words (channels 2cp,2cp+1 packed)
#define CPSTRIDE (18 * 68)             // 1224 words per cp plane
#define XS2_SIZE (16 * CPSTRIDE)       // 19584 words (all 32 channels)
#define SMEM_BYTES (XS2_SIZE * 4)      // 78336 B -> 2 blocks/SM (156.7KB <= 227KB)

// fused weights, fp16 frag layout: g_w2[((b*2+cg)*27+s)*32+lane][16 u32]
// word r = nf*2+half : half2{ w'[o][cA], w'[o][cA+1] },
//   o = nf*8 + (lane>>2), cA = cg*16 + half*8 + 2*(lane&3)
__device__ uint32_t g_w2[4 * 2 * 27 * 32 * 16];   // 110592 u32

__device__ __forceinline__ uint32_t smem_u32(const void* p) {
    uint32_t a;
    asm("{ .reg .u64 t; cvta.to.shared.u64 t, %1; cvt.u32.u64 %0, t; }" : "=r"(a) : "l"(p));
    return a;
}
__device__ __forceinline__ uint32_t lds32(uint32_t a) {
    uint32_t v; asm volatile("ld.shared.b32 %0, [%1];" : "=r"(v) : "r"(a)); return v;
}
__device__ __forceinline__ void mma_f16(float* c,
                                        uint32_t a0, uint32_t a1, uint32_t a2, uint32_t a3,
                                        uint32_t b0, uint32_t b1) {
    asm volatile("mma.sync.aligned.m16n8k16.row.col.f32.f16.f16.f32 "
                 "{%0,%1,%2,%3}, {%4,%5,%6,%7}, {%8,%9}, {%0,%1,%2,%3};"
                 : "+f"(c[0]), "+f"(c[1]), "+f"(c[2]), "+f"(c[3])
                 : "r"(a0), "r"(a1), "r"(a2), "r"(a3), "r"(b0), "r"(b1));
}

// ---------- init: w'[b,o,c,s] = sum_t weight[o,c,t]*stencils[b,t,s] -> fp16 frags ----------
__global__ void init_w2_kernel(const float* __restrict__ weight,
                               const float* __restrict__ stencils) {
    int idx  = blockIdx.x * 256 + threadIdx.x;   // 0 .. 110591
    int r    = idx & 15;
    int lane = (idx >> 4) & 31;
    int s    = (idx >> 9) % 27;
    int rest = (idx >> 9) / 27;                  // b*2 + cg
    int cg = rest & 1, b = rest >> 1;
    int nf = r >> 1, half = r & 1;
    int o  = nf * 8 + (lane >> 2);
    int cA = cg * 16 + half * 8 + 2 * (lane & 3);
    float va = 0.f, vb = 0.f;
    #pragma unroll
    for (int t = 0; t < TT; t++) {
        float st = stencils[(b * TT + t) * 27 + s];
        va += weight[(o * CIN + cA) * TT + t] * st;
        vb += weight[(o * CIN + cA + 1) * TT + t] * st;
    }
    __half2 h = __floats2half2_rn(va, vb);
    g_w2[idx] = *reinterpret_cast<uint32_t*>(&h);
}

__global__ __launch_bounds__(256, 2)
void stencilconv3d_kernel(const float* __restrict__ x,
                          const float* __restrict__ bias,
                          float* __restrict__ out) {
    extern __shared__ uint32_t sm[];
    const uint32_t smb = smem_u32(sm);

    const int h0  = blockIdx.x;   // 0..15 (4 output h rows)
    const int d0  = blockIdx.y;   // 0..31
    const int bz  = blockIdx.z;   // 0..3
    const int tid = threadIdx.x;
    const int wid = tid >> 5;     // 0..7
    const int lane = tid & 31;

    // warp mapping: hl = h row (0..3), oh = o half (0..1)
    const int hl = wid >> 1;
    const int oh = wid & 1;

    // thread-invariant part of A-frag address (bytes); warp's h row = hl
    const uint32_t poff = smb + (uint32_t)((lane & 3) * CPSTRIDE + hl * 68
                                           + (lane >> 2)) * 4u;

    float acc[4][4][4];           // [m-frag(16 w each)][n-frag(8 o, this half)][c]
    #pragma unroll
    for (int i = 0; i < 4; i++)
        #pragma unroll
        for (int j = 0; j < 4; j++)
            #pragma unroll
            for (int c = 0; c < 4; c++) acc[i][j][c] = 0.f;

    const size_t x_plane = (size_t)DDIM * HDIM * WDIM;
    const int hbase = h0 * 4 - 1;

    // ---- load entire x tile: 32 channels as 16 half2 planes, 18 rows x 68 w ----
    {
        const float* xc = x + (size_t)bz * CIN * x_plane;
        int wc = tid % 68;
        int hq = tid / 68;           // 0..3
        int dz = 0, cp = 0;
        for (int idx = tid; idx < XS2_SIZE; idx += 256) {
            int dg = d0 + dz - 1;
            int hg = hbase + hq;
            int wg = wc - 1;
            float v0 = 0.f, v1 = 0.f;
            if (wc < 66 && (unsigned)dg < DDIM && (unsigned)hg < HDIM && (unsigned)wg < WDIM) {
                const float* p0 = xc + (size_t)(2 * cp) * x_plane
                                + ((size_t)dg * HDIM + hg) * WDIM + wg;
                v0 = p0[0];
                v1 = p0[x_plane];
            }
            __half2 h = __floats2half2_rn(v0, v1);
            sm[idx] = *reinterpret_cast<uint32_t*>(&h);
            // advance by 256 = 3*68 + 52
            wc += 52; hq += 3;
            if (wc >= 68) { wc -= 68; hq++; }
            if (hq >= 6)  { hq -= 6; dz++; }
            if (dz >= 3)  { dz -= 3; cp++; }
        }
    }
    __syncthreads();   // the ONLY block barrier

    // ---- GEMM: 54 k16-steps (2 cg x 27 s), fully unrolled ----
    const uint4* wp = (const uint4*)g_w2
                    + ((size_t)(bz * 2) * 27 * 32 + lane) * 4 + oh * 2;
    #pragma unroll
    for (int cg = 0; cg < 2; cg++) {
        const uint32_t poffc = poff + (uint32_t)(cg * 8 * CPSTRIDE) * 4u;
        #pragma unroll
        for (int s = 0; s < 27; s++) {
            const int rowoff = (((s / 9) * 6 + ((s % 9) / 3)) * 68 + (s % 3)) * 4;
            uint32_t af[4][4];
            #pragma unroll
            for (int mf = 0; mf < 4; mf++) {
                uint32_t ab = poffc + (uint32_t)rowoff + (uint32_t)mf * 64u;
                af[mf][0] = lds32(ab);
                af[mf][1] = lds32(ab + 32u);                 // +8 w points
                af[mf][2] = lds32(ab + 4u * CPSTRIDE * 4u);  // +4 cp planes (k+8)
                af[mf][3] = lds32(ab + 4u * CPSTRIDE * 4u + 32u);
            }
            const uint4* wps = wp + (size_t)(cg * 27 + s) * 128;  // 32 lanes * 4 uint4
            uint4 q0 = __ldg(wps + 0);      // nf_local 0,1
            uint4 q1 = __ldg(wps + 1);      // nf_local 2,3
            #pragma unroll
            for (int mf = 0; mf < 4; mf++) {
                mma_f16(acc[mf][0], af[mf][0], af[mf][1], af[mf][2], af[mf][3], q0.x, q0.y);
                mma_f16(acc[mf][1], af[mf][0], af[mf][1], af[mf][2], af[mf][3], q0.z, q0.w);
                mma_f16(acc[mf][2], af[mf][0], af[mf][1], af[mf][2], af[mf][3], q1.x, q1.y);
                mma_f16(acc[mf][3], af[mf][0], af[mf][1], af[mf][2], af[mf][3], q1.z, q1.w);
            }
        }
    }

    // ---- epilogue: registers -> gmem, + bias ----
    {
        const size_t ostride = (size_t)DDIM * HDIM * WDIM;
        const int h = h0 * 4 + hl;
        const size_t obase = (size_t)bz * COUT * ostride
                           + (size_t)d0 * HDIM * WDIM + (size_t)h * WDIM;
        #pragma unroll
        for (int nf = 0; nf < 4; nf++) {
            int o0 = oh * 32 + nf * 8 + (lane & 3) * 2;
            float bv0 = __ldg(&bias[o0]);
            float bv1 = __ldg(&bias[o0 + 1]);
            #pragma unroll
            for (int mf = 0; mf < 4; mf++) {
                #pragma unroll
                for (int cc = 0; cc < 4; cc++) {
                    float sv = acc[mf][nf][cc];
                    int o = o0 + (cc & 1);
                    int w = mf * 16 + (lane >> 2) + ((cc >> 1) & 1) * 8;
                    out[obase + (size_t)o * ostride + w]
                        = sv + ((cc & 1) ? bv1 : bv0);
                }
            }
        }
    }
}

extern "C" void kernel_launch(void* const* d_in, const int* in_sizes, int n_in,
                              void* d_out, int out_size) {
    const float* x        = (const float*)d_in[0];
    const float* stencils = (const float*)d_in[1];
    const float* weight   = (const float*)d_in[2];
    const float* bias     = (const float*)d_in[3];
    float* out = (float*)d_out;

    init_w2_kernel<<<432, 256>>>(weight, stencils);

    cudaFuncSetAttribute(stencilconv3d_kernel,
                         cudaFuncAttributeMaxDynamicSharedMemorySize, SMEM_BYTES);
    dim3 grid(HDIM / 4, DDIM, 4);   // 16 x 32 x 4 = 2048 blocks
    stencilconv3d_kernel<<<grid, 256, SMEM_BYTES>>>(x, bias, out);
}

// round 15
// speedup vs baseline: 3.7725x; 1.1761x over previous
#include <cuda_runtime.h>
#include <cuda_fp16.h>
#include <cstdint>

#define CIN   32
#define COUT  64
#define TT    8
#define DDIM  32
#define HDIM  64
#define WDIM  64

// xs2: [row(18 = 3d x 6h)][wc(68)][cp(16)] half2 words, 16B quarters XOR-swizzled:
//   word(row,wc,cp) = (row*68 + wc)*16 + (q ^ ((wc>>1)&3))*4 + (cp&3),  q = cp>>2
#define NPOS      (18 * 68)            // 1224 positions
#define XS2_SIZE  (NPOS * 16)          // 19584 words
#define SMEM_BYTES (XS2_SIZE * 4)      // 78336 B -> 2 blocks/SM

// fused weights, fp16 frag layout: g_w2[((b*2+cg)*27+s)*32+lane][16 u32]
__device__ uint32_t g_w2[4 * 2 * 27 * 32 * 16];   // 110592 u32

__device__ __forceinline__ uint32_t smem_u32(const void* p) {
    uint32_t a;
    asm("{ .reg .u64 t; cvta.to.shared.u64 t, %1; cvt.u32.u64 %0, t; }" : "=r"(a) : "l"(p));
    return a;
}
__device__ __forceinline__ void ldsm_x4(uint32_t* r, uint32_t a) {
    asm volatile("ldmatrix.sync.aligned.m8n8.x4.shared.b16 {%0,%1,%2,%3}, [%4];"
                 : "=r"(r[0]), "=r"(r[1]), "=r"(r[2]), "=r"(r[3]) : "r"(a));
}
__device__ __forceinline__ void sts128(uint32_t a, uint32_t v0, uint32_t v1,
                                       uint32_t v2, uint32_t v3) {
    asm volatile("st.shared.v4.b32 [%0], {%1,%2,%3,%4};"
                 :: "r"(a), "r"(v0), "r"(v1), "r"(v2), "r"(v3));
}
__device__ __forceinline__ void mma_f16(float* c,
                                        uint32_t a0, uint32_t a1, uint32_t a2, uint32_t a3,
                                        uint32_t b0, uint32_t b1) {
    asm volatile("mma.sync.aligned.m16n8k16.row.col.f32.f16.f16.f32 "
                 "{%0,%1,%2,%3}, {%4,%5,%6,%7}, {%8,%9}, {%0,%1,%2,%3};"
                 : "+f"(c[0]), "+f"(c[1]), "+f"(c[2]), "+f"(c[3])
                 : "r"(a0), "r"(a1), "r"(a2), "r"(a3), "r"(b0), "r"(b1));
}

// ---------- init: w'[b,o,c,s] = sum_t weight[o,c,t]*stencils[b,t,s] -> fp16 frags ----------
__global__ void init_w2_kernel(const float* __restrict__ weight,
                               const float* __restrict__ stencils) {
    int idx  = blockIdx.x * 256 + threadIdx.x;   // 0 .. 110591
    int r    = idx & 15;
    int lane = (idx >> 4) & 31;
    int s    = (idx >> 9) % 27;
    int rest = (idx >> 9) / 27;                  // b*2 + cg
    int cg = rest & 1, b = rest >> 1;
    int nf = r >> 1, half = r & 1;
    int o  = nf * 8 + (lane >> 2);
    int cA = cg * 16 + half * 8 + 2 * (lane & 3);
    float va = 0.f, vb = 0.f;
    #pragma unroll
    for (int t = 0; t < TT; t++) {
        float st = stencils[(b * TT + t) * 27 + s];
        va += weight[(o * CIN + cA) * TT + t] * st;
        vb += weight[(o * CIN + cA + 1) * TT + t] * st;
    }
    __half2 h = __floats2half2_rn(va, vb);
    g_w2[idx] = *reinterpret_cast<uint32_t*>(&h);
}

__global__ __launch_bounds__(256, 2)
void stencilconv3d_kernel(const float* __restrict__ x,
                          const float* __restrict__ bias,
                          float* __restrict__ out) {
    extern __shared__ uint32_t sm[];
    const uint32_t smb = smem_u32(sm);

    const int h0  = blockIdx.x;   // 0..15 (4 output h rows)
    const int d0  = blockIdx.y;   // 0..31
    const int bz  = blockIdx.z;   // 0..3
    const int tid = threadIdx.x;
    const int wid = tid >> 5;     // 0..7
    const int lane = tid & 31;

    // warp mapping: hl = h row (0..3), oh = o half (0..1)
    const int hl = wid >> 1;
    const int oh = wid & 1;

    const size_t x_plane = (size_t)DDIM * HDIM * WDIM;
    const int hbase = h0 * 4 - 1;

    // ---- load x tile: per position, 32 channels -> 16 half2, swizzled quarters ----
    {
        const float* xc = x + (size_t)bz * CIN * x_plane;
        for (int p = tid; p < NPOS; p += 256) {
            int row = p / 68, wc = p - row * 68;
            int dz = row / 6,  hq = row - dz * 6;
            int dg = d0 + dz - 1;
            int hg = hbase + hq;
            int wg = wc - 1;
            uint32_t hw[16];
            if (wc < 66 && (unsigned)dg < DDIM && (unsigned)hg < HDIM && (unsigned)wg < WDIM) {
                const float* pp = xc + ((size_t)dg * HDIM + hg) * WDIM + wg;
                #pragma unroll
                for (int j = 0; j < 16; j++) {
                    float v0 = pp[(size_t)(2 * j) * x_plane];
                    float v1 = pp[(size_t)(2 * j + 1) * x_plane];
                    __half2 h = __floats2half2_rn(v0, v1);
                    hw[j] = *reinterpret_cast<uint32_t*>(&h);
                }
            } else {
                #pragma unroll
                for (int j = 0; j < 16; j++) hw[j] = 0u;
            }
            const int fsw = (wc >> 1) & 3;
            uint32_t base = smb + (uint32_t)(p * 16) * 4u;
            #pragma unroll
            for (int q = 0; q < 4; q++) {
                uint32_t a = base + (uint32_t)((q ^ fsw) * 4) * 4u;
                sts128(a, hw[q * 4 + 0], hw[q * 4 + 1], hw[q * 4 + 2], hw[q * 4 + 3]);
            }
        }
    }
    __syncthreads();   // the ONLY block barrier

    float acc[4][4][4];           // [m-frag(16 w each)][n-frag(8 o, this half)][c]
    #pragma unroll
    for (int i = 0; i < 4; i++)
        #pragma unroll
        for (int j = 0; j < 4; j++)
            #pragma unroll
            for (int c = 0; c < 4; c++) acc[i][j][c] = 0.f;

    // per-lane ldmatrix geometry
    const int wbase = ((lane >> 3) & 1) * 8 + (lane & 7);  // w within 16-w m-tile
    const int qsel  = lane >> 4;                           // 0 = k0-7, 1 = k8-15

    // ---- GEMM: 54 k16-steps (2 cg x 27 s), A via ldmatrix.x4 ----
    const uint4* wp = (const uint4*)g_w2
                    + ((size_t)(bz * 2) * 27 * 32 + lane) * 4 + oh * 2;
    #pragma unroll 1
    for (int cg = 0; cg < 2; cg++) {
        const int qb = qsel + cg * 2;
        #pragma unroll
        for (int s = 0; s < 27; s++) {
            const int srow = (s / 9) * 6 + ((s % 9) / 3) + hl;
            const int sw   = s % 3;
            const int wcL  = wbase + sw;
            const int qp   = qb ^ ((wcL >> 1) & 3);
            uint32_t a0addr = smb + (uint32_t)(((srow * 68 + wcL) * 16) + qp * 4) * 4u;
            uint32_t af[4][4];
            #pragma unroll
            for (int mf = 0; mf < 4; mf++)
                ldsm_x4(af[mf], a0addr + (uint32_t)mf * 1024u);
            const uint4* wps = wp + (size_t)(cg * 27 + s) * 128;
            uint4 q0 = __ldg(wps + 0);      // nf_local 0,1
            uint4 q1 = __ldg(wps + 1);      // nf_local 2,3
            #pragma unroll
            for (int mf = 0; mf < 4; mf++) {
                mma_f16(acc[mf][0], af[mf][0], af[mf][1], af[mf][2], af[mf][3], q0.x, q0.y);
                mma_f16(acc[mf][1], af[mf][0], af[mf][1], af[mf][2], af[mf][3], q0.z, q0.w);
                mma_f16(acc[mf][2], af[mf][0], af[mf][1], af[mf][2], af[mf][3], q1.x, q1.y);
                mma_f16(acc[mf][3], af[mf][0], af[mf][1], af[mf][2], af[mf][3], q1.z, q1.w);
            }
        }
    }

    // ---- epilogue: registers -> gmem, + bias ----
    {
        const size_t ostride = (size_t)DDIM * HDIM * WDIM;
        const int h = h0 * 4 + hl;
        const size_t obase = (size_t)bz * COUT * ostride
                           + (size_t)d0 * HDIM * WDIM + (size_t)h * WDIM;
        #pragma unroll
        for (int nf = 0; nf < 4; nf++) {
            int o0 = oh * 32 + nf * 8 + (lane & 3) * 2;
            float bv0 = __ldg(&bias[o0]);
            float bv1 = __ldg(&bias[o0 + 1]);
            #pragma unroll
            for (int mf = 0; mf < 4; mf++) {
                #pragma unroll
                for (int cc = 0; cc < 4; cc++) {
                    float sv = acc[mf][nf][cc];
                    int o = o0 + (cc & 1);
                    int w = mf * 16 + (lane >> 2) + ((cc >> 1) & 1) * 8;
                    out[obase + (size_t)o * ostride + w]
                        = sv + ((cc & 1) ? bv1 : bv0);
                }
            }
        }
    }
}

extern "C" void kernel_launch(void* const* d_in, const int* in_sizes, int n_in,
                              void* d_out, int out_size) {
    const float* x        = (const float*)d_in[0];
    const float* stencils = (const float*)d_in[1];
    const float* weight   = (const float*)d_in[2];
    const float* bias     = (const float*)d_in[3];
    float* out = (float*)d_out;

    init_w2_kernel<<<432, 256>>>(weight, stencils);

    cudaFuncSetAttribute(stencilconv3d_kernel,
                         cudaFuncAttributeMaxDynamicSharedMemorySize, SMEM_BYTES);
    dim3 grid(HDIM / 4, DDIM, 4);   // 16 x 32 x 4 = 2048 blocks
    stencilconv3d_kernel<<<grid, 256, SMEM_BYTES>>>(x, bias, out);
}